// round 4
// baseline (speedup 1.0000x reference)
#include <cuda_runtime.h>
#include <cuda_bf16.h>
#include <math.h>

// Problem constants
#define BATCH  4
#define DIM    192
#define HH     128
#define WW     128
#define HW     16384            // 128*128
#define HEADS  4
#define CH     48               // DIM / HEADS
#define MQKV   576              // 3*DIM
#define KDIM   192              // reduction dim of 1x1 convs
#define BHN    16               // BATCH*HEADS

// ---------------- scratch (device globals; no allocation allowed) ----------
__device__ __align__(16) float g_qkv[(size_t)BATCH * MQKV * HW];  // conv1x1 qkv output
__device__ __align__(16) float g_dw [(size_t)BATCH * MQKV * HW];  // after depthwise 3x3
__device__ __align__(16) float g_S   [BHN * CH * CH];             // raw q.k^T partial sums
__device__ __align__(16) float g_norm[BHN * 96];                  // sumsq: q rows then k rows
__device__ __align__(16) float g_comb[BHN * CH * CH];             // combined attention weights
__device__ __align__(16) float g_ao  [(size_t)BATCH * DIM * HW];  // comb @ v

// ---------------- GEMM: Y[b][m][n] = sum_k W[m][k] * X[b][k][n] ------------
// M runtime (576 or 192), K=192, N=16384. BM=128, BN=64, BK=16, 256 threads,
// 8x4 register tile per thread.
#define BM 128
#define BN 64
#define BK 16

__global__ __launch_bounds__(256) void gemm_conv1x1(
    const float* __restrict__ Wt, const float* __restrict__ X,
    float* __restrict__ Y, int M)
{
    const int b  = blockIdx.z;
    const int m0 = blockIdx.y * BM;
    const int n0 = blockIdx.x * BN;
    const float* Xb = X + (size_t)b * KDIM * HW;
    float*       Yb = Y + (size_t)b * M * HW;

    __shared__ float As[BK][BM];
    __shared__ float Bs[BK][BN];

    const int tid = threadIdx.x;
    const int tx  = tid & 15;    // n-group: 16 groups of 4 cols
    const int ty  = tid >> 4;    // m-group: 16 groups of 8 rows

    float acc[8][4];
    #pragma unroll
    for (int i = 0; i < 8; ++i)
        #pragma unroll
        for (int j = 0; j < 4; ++j) acc[i][j] = 0.f;

    for (int k0 = 0; k0 < KDIM; k0 += BK) {
        // A tile: W[m0..m0+127][k0..k0+15] -> As[k][m] (transposed)
        {
            const int r  = tid >> 2;           // 0..63
            const int c4 = (tid & 3) << 2;     // 0,4,8,12
            #pragma unroll
            for (int p = 0; p < 2; ++p) {
                const int m = m0 + r + p * 64;
                float4 v = make_float4(0.f, 0.f, 0.f, 0.f);
                if (m < M) v = *(const float4*)(Wt + (size_t)m * KDIM + k0 + c4);
                As[c4 + 0][r + p * 64] = v.x;
                As[c4 + 1][r + p * 64] = v.y;
                As[c4 + 2][r + p * 64] = v.z;
                As[c4 + 3][r + p * 64] = v.w;
            }
        }
        // B tile: X[k0+kk][n0..n0+63]
        {
            const int kk = tid >> 4;
            const int nn = (tid & 15) << 2;
            *(float4*)&Bs[kk][nn] =
                *(const float4*)(Xb + (size_t)(k0 + kk) * HW + n0 + nn);
        }
        __syncthreads();

        #pragma unroll
        for (int kk = 0; kk < BK; ++kk) {
            float a[8], bf[4];
            #pragma unroll
            for (int i = 0; i < 8; ++i) a[i] = As[kk][ty * 8 + i];
            #pragma unroll
            for (int j = 0; j < 4; ++j) bf[j] = Bs[kk][tx * 4 + j];
            #pragma unroll
            for (int i = 0; i < 8; ++i)
                #pragma unroll
                for (int j = 0; j < 4; ++j)
                    acc[i][j] = fmaf(a[i], bf[j], acc[i][j]);
        }
        __syncthreads();
    }

    #pragma unroll
    for (int i = 0; i < 8; ++i) {
        const int m = m0 + ty * 8 + i;
        if (m < M) {
            float4 v = make_float4(acc[i][0], acc[i][1], acc[i][2], acc[i][3]);
            *(float4*)(Yb + (size_t)m * HW + n0 + tx * 4) = v;
        }
    }
}

// ---------------- depthwise 3x3, pad 1 -------------------------------------
__global__ __launch_bounds__(128) void dwconv3x3(
    const float* __restrict__ in, const float* __restrict__ wdw,
    float* __restrict__ out)
{
    const int h  = blockIdx.x;          // 0..127
    const int bc = blockIdx.y;          // 0..BATCH*MQKV-1
    const int w  = threadIdx.x;         // 0..127
    const int ch = bc % MQKV;
    const float* wp   = wdw + ch * 9;
    const float* base = in + (size_t)bc * HW;

    float s = 0.f;
    #pragma unroll
    for (int dy = -1; dy <= 1; ++dy) {
        const int hh = h + dy;
        if (hh < 0 || hh >= HH) continue;
        #pragma unroll
        for (int dx = -1; dx <= 1; ++dx) {
            const int ww = w + dx;
            if (ww < 0 || ww >= WW) continue;
            s = fmaf(base[hh * WW + ww], wp[(dy + 1) * 3 + (dx + 1)], s);
        }
    }
    out[(size_t)bc * HW + h * WW + w] = s;
}

// ---------------- zero the accumulation buffers ----------------------------
__global__ void zero_small()
{
    const int i = blockIdx.x * 256 + threadIdx.x;
    if (i < BHN * CH * CH) g_S[i] = 0.f;
    if (i < BHN * 96)      g_norm[i] = 0.f;
}

// ---------------- attn partials: S = q k^T, plus row sumsq -----------------
// grid (16 bh, 64 segments of 256 n), 256 threads. Each thread owns a 3x3
// patch of the 48x48 output.
// Shared row stride 68 floats = 272 bytes (multiple of 16) so float4
// stores into shared are aligned for every row.
__global__ __launch_bounds__(256) void attn_partial()
{
    const int bh  = blockIdx.x;
    const int seg = blockIdx.y;
    const int b   = bh >> 2;
    const int hh  = bh & 3;
    const float* qbase = g_dw + ((size_t)b * MQKV + hh * CH) * HW;
    const float* kbase = g_dw + ((size_t)b * MQKV + DIM + hh * CH) * HW;
    const int n0 = seg * 256;

    __shared__ __align__(16) float qs[48][68];
    __shared__ __align__(16) float ks[48][68];

    const int tid = threadIdx.x;
    const int i0  = (tid >> 4) * 3;
    const int j0  = (tid & 15) * 3;

    float acc[3][3];
    #pragma unroll
    for (int i = 0; i < 3; ++i)
        #pragma unroll
        for (int j = 0; j < 3; ++j) acc[i][j] = 0.f;
    float sq = 0.f;

    for (int c = 0; c < 4; ++c) {
        const int nb = n0 + c * 64;
        for (int l = tid; l < 48 * 16; l += 256) {   // float4 granules
            const int row  = l >> 4;
            const int col4 = (l & 15) << 2;
            *(float4*)&qs[row][col4] =
                *(const float4*)(qbase + (size_t)row * HW + nb + col4);
            *(float4*)&ks[row][col4] =
                *(const float4*)(kbase + (size_t)row * HW + nb + col4);
        }
        __syncthreads();
        #pragma unroll 4
        for (int t = 0; t < 64; ++t) {
            const float qa0 = qs[i0 + 0][t], qa1 = qs[i0 + 1][t], qa2 = qs[i0 + 2][t];
            const float kb0 = ks[j0 + 0][t], kb1 = ks[j0 + 1][t], kb2 = ks[j0 + 2][t];
            acc[0][0] = fmaf(qa0, kb0, acc[0][0]);
            acc[0][1] = fmaf(qa0, kb1, acc[0][1]);
            acc[0][2] = fmaf(qa0, kb2, acc[0][2]);
            acc[1][0] = fmaf(qa1, kb0, acc[1][0]);
            acc[1][1] = fmaf(qa1, kb1, acc[1][1]);
            acc[1][2] = fmaf(qa1, kb2, acc[1][2]);
            acc[2][0] = fmaf(qa2, kb0, acc[2][0]);
            acc[2][1] = fmaf(qa2, kb1, acc[2][1]);
            acc[2][2] = fmaf(qa2, kb2, acc[2][2]);
            if (tid < 96) {
                const float v = (tid < 48) ? qs[tid][t] : ks[tid - 48][t];
                sq = fmaf(v, v, sq);
            }
        }
        __syncthreads();
    }

    float* Sp = g_S + bh * CH * CH;
    #pragma unroll
    for (int i = 0; i < 3; ++i)
        #pragma unroll
        for (int j = 0; j < 3; ++j)
            atomicAdd(&Sp[(i0 + i) * CH + (j0 + j)], acc[i][j]);
    if (tid < 96) atomicAdd(&g_norm[bh * 96 + tid], sq);
}

// ---------------- finalize: normalize, per-row topk/softmax, combine -------
// k values: int(48*rate) with rates evaluated in IEEE double:
//   48*(1/2)=24; 48*(2.0/3) = 32 - 2^-49, exactly halfway between
//   (32 - 2^-48) and 32 -> round-to-nearest-EVEN gives 32.0 -> int = 32;
//   48*0.75=36; 48*(4.0/5)=38.4000000000000021 -> 38.
__global__ void finalize_comb(const float* __restrict__ temperature,
                              const float* __restrict__ attn_w)
{
    const int bh = blockIdx.x;
    const int hh = bh & 3;
    const int i  = threadIdx.x;
    if (i >= CH) return;

    float a[CH];
    const float nq = fmaxf(sqrtf(g_norm[bh * 96 + i]), 1e-12f);
    const float tmp = temperature[hh];
    for (int j = 0; j < CH; ++j) {
        const float nk = fmaxf(sqrtf(g_norm[bh * 96 + 48 + j]), 1e-12f);
        a[j] = g_S[bh * CH * CH + i * CH + j] * tmp / (nq * nk);
    }

    // rank with index-order tiebreak (matches jax.lax.top_k)
    int rank[CH];
    for (int j = 0; j < CH; ++j) {
        int r = 0;
        for (int l = 0; l < CH; ++l)
            if (a[l] > a[j] || (a[l] == a[j] && l < j)) r++;
        rank[j] = r;
    }

    float comb[CH];
    for (int j = 0; j < CH; ++j) comb[j] = 0.f;

    const int kvals[4] = {24, 32, 36, 38};
    for (int r = 0; r < 4; ++r) {
        const int kv = kvals[r];
        float m = -INFINITY;
        for (int j = 0; j < CH; ++j)
            if (rank[j] < kv) m = fmaxf(m, a[j]);
        float e[CH];
        float ssum = 0.f;
        for (int j = 0; j < CH; ++j) {
            e[j] = (rank[j] < kv) ? expf(a[j] - m) : 0.f;
            ssum += e[j];
        }
        const float wgt = attn_w[r] / ssum;
        for (int j = 0; j < CH; ++j) comb[j] = fmaf(e[j], wgt, comb[j]);
    }

    for (int j = 0; j < CH; ++j)
        g_comb[bh * CH * CH + i * CH + j] = comb[j];
}

// ---------------- out = comb @ v -------------------------------------------
// grid (16 bh, 64 tiles of 256 n), 256 threads; each thread handles one n.
__global__ __launch_bounds__(256) void attn_apply()
{
    const int bh = blockIdx.x;
    const int b  = bh >> 2;
    const int hh = bh & 3;

    __shared__ float cs[CH][CH];
    const int tid = threadIdx.x;
    for (int l = tid; l < CH * CH; l += 256)
        cs[l / CH][l % CH] = g_comb[bh * CH * CH + l];
    __syncthreads();

    const int n = blockIdx.y * 256 + tid;
    const float* vb = g_dw + ((size_t)b * MQKV + 2 * DIM + hh * CH) * HW + n;
    float v[CH];
    #pragma unroll
    for (int d = 0; d < CH; ++d) v[d] = vb[(size_t)d * HW];

    float* ob = g_ao + ((size_t)b * DIM + hh * CH) * HW + n;
    #pragma unroll 4
    for (int c = 0; c < CH; ++c) {
        float s = 0.f;
        #pragma unroll
        for (int d = 0; d < CH; ++d) s = fmaf(cs[c][d], v[d], s);
        ob[(size_t)c * HW] = s;
    }
}

// ---------------- launch ----------------------------------------------------
extern "C" void kernel_launch(void* const* d_in, const int* in_sizes, int n_in,
                              void* d_out, int out_size)
{
    const float* x           = (const float*)d_in[0];  // [4,192,128,128]
    const float* w_qkv       = (const float*)d_in[1];  // [576,192]
    const float* w_dw        = (const float*)d_in[2];  // [576,9]
    const float* w_proj      = (const float*)d_in[3];  // [192,192]
    const float* temperature = (const float*)d_in[4];  // [4]
    const float* attn_w      = (const float*)d_in[5];  // [4]
    float* out = (float*)d_out;

    float* qkv; cudaGetSymbolAddress((void**)&qkv, g_qkv);
    float* dw;  cudaGetSymbolAddress((void**)&dw,  g_dw);
    float* ao;  cudaGetSymbolAddress((void**)&ao,  g_ao);

    // 1. qkv = w_qkv @ x   (per batch GEMM 576 x 16384 x 192)
    gemm_conv1x1<<<dim3(HW / BN, (MQKV + BM - 1) / BM, BATCH), 256>>>(
        w_qkv, x, qkv, MQKV);

    // 2. depthwise 3x3
    dwconv3x3<<<dim3(HH, BATCH * MQKV), 128>>>(qkv, w_dw, dw);

    // 3. zero accumulators, then attn partials (S, norms)
    zero_small<<<(BHN * CH * CH + 255) / 256, 256>>>();
    attn_partial<<<dim3(BHN, 64), 256>>>();

    // 4. finalize combined attention weights (topk + softmax + weighted sum)
    finalize_comb<<<BHN, 64>>>(temperature, attn_w);

    // 5. out = comb @ v
    attn_apply<<<dim3(BHN, HW / 256), 256>>>();

    // 6. projection conv1x1 -> d_out
    gemm_conv1x1<<<dim3(HW / BN, (DIM + BM - 1) / BM, BATCH), 256>>>(
        w_proj, ao, out, DIM);
}

// round 5
// speedup vs baseline: 1.0788x; 1.0788x over previous
#include <cuda_runtime.h>
#include <cuda_bf16.h>
#include <math.h>

// Problem constants
#define BATCH  4
#define DIM    192
#define HH     128
#define WW     128
#define HW     16384            // 128*128
#define HEADS  4
#define CH     48               // DIM / HEADS
#define MQKV   576              // 3*DIM
#define KDIM   192              // reduction dim of 1x1 convs
#define BHN    16               // BATCH*HEADS

typedef unsigned long long u64;

// packed f32x2 helpers (Blackwell): d = a*b + d on both 32-bit lanes
__device__ __forceinline__ void ffma2(u64& d, u64 a, u64 b) {
    asm("fma.rn.f32x2 %0, %1, %2, %0;" : "+l"(d) : "l"(a), "l"(b));
}
__device__ __forceinline__ u64 bcast2(float v) {
    u64 r;
    asm("mov.b64 %0, {%1, %1};" : "=l"(r) : "r"(__float_as_uint(v)));
    return r;
}
__device__ __forceinline__ float lo2(u64 v) {
    return __uint_as_float((unsigned)(v & 0xffffffffull));
}
__device__ __forceinline__ float hi2(u64 v) {
    return __uint_as_float((unsigned)(v >> 32));
}
__device__ __forceinline__ float hsum2(u64 v) { return lo2(v) + hi2(v); }

// ---------------- scratch (device globals; no allocation allowed) ----------
__device__ __align__(16) float g_qkv[(size_t)BATCH * MQKV * HW];  // conv1x1 qkv output
__device__ __align__(16) float g_dw [(size_t)BATCH * MQKV * HW];  // after depthwise 3x3
__device__ __align__(16) float g_S   [BHN * CH * CH];             // raw q.k^T partial sums
__device__ __align__(16) float g_norm[BHN * 96];                  // sumsq: q rows then k rows
__device__ __align__(16) float g_comb[BHN * CH * CH];             // combined attention weights
__device__ __align__(16) float g_ao  [(size_t)BATCH * DIM * HW];  // comb @ v

// ---------------- GEMM: Y[b][m][n] = sum_k W[m][k] * X[b][k][n] ------------
// M runtime (576 or 192), K=192, N=16384. BM=128, BN=64, BK=16, 256 threads.
// 8x4 register tile per thread, accumulated as f32x2 pairs along M.
#define BM 128
#define BN 64
#define BK 16

__global__ __launch_bounds__(256) void gemm_conv1x1(
    const float* __restrict__ Wt, const float* __restrict__ X,
    float* __restrict__ Y, int M)
{
    const int b  = blockIdx.z;
    const int m0 = blockIdx.y * BM;
    const int n0 = blockIdx.x * BN;
    const float* Xb = X + (size_t)b * KDIM * HW;
    float*       Yb = Y + (size_t)b * M * HW;

    __shared__ __align__(16) float As[BK][BM];
    __shared__ __align__(16) float Bs[BK][BN];

    const int tid = threadIdx.x;
    const int tx  = tid & 15;    // n-group: 16 groups of 4 cols
    const int ty  = tid >> 4;    // m-group: 16 groups of 8 rows

    // acc2[i2][j] packs rows {ty*8+2*i2, ty*8+2*i2+1} for column tx*4+j
    u64 acc2[4][4];
    #pragma unroll
    for (int i = 0; i < 4; ++i)
        #pragma unroll
        for (int j = 0; j < 4; ++j) acc2[i][j] = 0ull;

    for (int k0 = 0; k0 < KDIM; k0 += BK) {
        // A tile: W[m0..m0+127][k0..k0+15] -> As[k][m] (transposed)
        {
            const int r  = tid >> 2;           // 0..63
            const int c4 = (tid & 3) << 2;     // 0,4,8,12
            #pragma unroll
            for (int p = 0; p < 2; ++p) {
                const int m = m0 + r + p * 64;
                float4 v = make_float4(0.f, 0.f, 0.f, 0.f);
                if (m < M) v = *(const float4*)(Wt + (size_t)m * KDIM + k0 + c4);
                As[c4 + 0][r + p * 64] = v.x;
                As[c4 + 1][r + p * 64] = v.y;
                As[c4 + 2][r + p * 64] = v.z;
                As[c4 + 3][r + p * 64] = v.w;
            }
        }
        // B tile: X[k0+kk][n0..n0+63]
        {
            const int kk = tid >> 4;
            const int nn = (tid & 15) << 2;
            *(float4*)&Bs[kk][nn] =
                *(const float4*)(Xb + (size_t)(k0 + kk) * HW + n0 + nn);
        }
        __syncthreads();

        #pragma unroll
        for (int kk = 0; kk < BK; ++kk) {
            u64 a2[4];
            #pragma unroll
            for (int i = 0; i < 4; ++i)   // LDS.64: m-pairs, 8B aligned (ty*8 even)
                a2[i] = *(const u64*)&As[kk][ty * 8 + 2 * i];
            u64 b2[4];
            #pragma unroll
            for (int j = 0; j < 4; ++j)
                b2[j] = bcast2(Bs[kk][tx * 4 + j]);
            #pragma unroll
            for (int i = 0; i < 4; ++i)
                #pragma unroll
                for (int j = 0; j < 4; ++j)
                    ffma2(acc2[i][j], a2[i], b2[j]);
        }
        __syncthreads();
    }

    #pragma unroll
    for (int i2 = 0; i2 < 4; ++i2) {
        const int m = m0 + ty * 8 + 2 * i2;
        if (m < M) {
            float4 v0 = make_float4(lo2(acc2[i2][0]), lo2(acc2[i2][1]),
                                    lo2(acc2[i2][2]), lo2(acc2[i2][3]));
            float4 v1 = make_float4(hi2(acc2[i2][0]), hi2(acc2[i2][1]),
                                    hi2(acc2[i2][2]), hi2(acc2[i2][3]));
            *(float4*)(Yb + (size_t)m * HW + n0 + tx * 4) = v0;
            *(float4*)(Yb + (size_t)(m + 1) * HW + n0 + tx * 4) = v1;
        }
    }
}

// ---------------- depthwise 3x3, pad 1 -------------------------------------
__global__ __launch_bounds__(128) void dwconv3x3(
    const float* __restrict__ in, const float* __restrict__ wdw,
    float* __restrict__ out)
{
    const int h  = blockIdx.x;          // 0..127
    const int bc = blockIdx.y;          // 0..BATCH*MQKV-1
    const int w  = threadIdx.x;         // 0..127
    const int ch = bc % MQKV;
    const float* wp   = wdw + ch * 9;
    const float* base = in + (size_t)bc * HW;

    float s = 0.f;
    #pragma unroll
    for (int dy = -1; dy <= 1; ++dy) {
        const int hh = h + dy;
        if (hh < 0 || hh >= HH) continue;
        #pragma unroll
        for (int dx = -1; dx <= 1; ++dx) {
            const int ww = w + dx;
            if (ww < 0 || ww >= WW) continue;
            s = fmaf(base[hh * WW + ww], wp[(dy + 1) * 3 + (dx + 1)], s);
        }
    }
    out[(size_t)bc * HW + h * WW + w] = s;
}

// ---------------- zero the accumulation buffers ----------------------------
__global__ void zero_small()
{
    const int i = blockIdx.x * 256 + threadIdx.x;
    if (i < BHN * CH * CH) g_S[i] = 0.f;
    if (i < BHN * 96)      g_norm[i] = 0.f;
}

// ---------------- attn partials: S = q k^T, plus row sumsq -----------------
// grid (16 bh, 64 segments of 256 n), 256 threads. Each thread owns a 3x3
// patch of the 48x48 output. Inner product packed pairwise along t (f32x2).
__global__ __launch_bounds__(256) void attn_partial()
{
    const int bh  = blockIdx.x;
    const int seg = blockIdx.y;
    const int b   = bh >> 2;
    const int hh  = bh & 3;
    const float* qbase = g_dw + ((size_t)b * MQKV + hh * CH) * HW;
    const float* kbase = g_dw + ((size_t)b * MQKV + DIM + hh * CH) * HW;
    const int n0 = seg * 256;

    __shared__ __align__(16) float qs[48][68];   // stride 272B (16B multiple)
    __shared__ __align__(16) float ks[48][68];

    const int tid = threadIdx.x;
    const int i0  = (tid >> 4) * 3;
    const int j0  = (tid & 15) * 3;

    u64 acc2[3][3];
    #pragma unroll
    for (int i = 0; i < 3; ++i)
        #pragma unroll
        for (int j = 0; j < 3; ++j) acc2[i][j] = 0ull;
    u64 sq2 = 0ull;

    for (int c = 0; c < 4; ++c) {
        const int nb = n0 + c * 64;
        for (int l = tid; l < 48 * 16; l += 256) {   // float4 granules
            const int row  = l >> 4;
            const int col4 = (l & 15) << 2;
            *(float4*)&qs[row][col4] =
                *(const float4*)(qbase + (size_t)row * HW + nb + col4);
            *(float4*)&ks[row][col4] =
                *(const float4*)(kbase + (size_t)row * HW + nb + col4);
        }
        __syncthreads();
        #pragma unroll 4
        for (int t = 0; t < 64; t += 2) {
            u64 qa[3], kb[3];
            #pragma unroll
            for (int i = 0; i < 3; ++i) qa[i] = *(const u64*)&qs[i0 + i][t];
            #pragma unroll
            for (int j = 0; j < 3; ++j) kb[j] = *(const u64*)&ks[j0 + j][t];
            #pragma unroll
            for (int i = 0; i < 3; ++i)
                #pragma unroll
                for (int j = 0; j < 3; ++j)
                    ffma2(acc2[i][j], qa[i], kb[j]);
            if (tid < 96) {
                const u64 v = (tid < 48) ? *(const u64*)&qs[tid][t]
                                         : *(const u64*)&ks[tid - 48][t];
                ffma2(sq2, v, v);
            }
        }
        __syncthreads();
    }

    float* Sp = g_S + bh * CH * CH;
    #pragma unroll
    for (int i = 0; i < 3; ++i)
        #pragma unroll
        for (int j = 0; j < 3; ++j)
            atomicAdd(&Sp[(i0 + i) * CH + (j0 + j)], hsum2(acc2[i][j]));
    if (tid < 96) atomicAdd(&g_norm[bh * 96 + tid], hsum2(sq2));
}

// ---------------- finalize: normalize, per-row topk/softmax, combine -------
// k values: int(48*rate) with rates evaluated in IEEE double:
//   48*(1/2)=24; 48*(2.0/3)=32 (round-to-even at halfway); 48*0.75=36;
//   48*(4.0/5)=38.4000000000000021 -> 38.
__global__ void finalize_comb(const float* __restrict__ temperature,
                              const float* __restrict__ attn_w)
{
    const int bh = blockIdx.x;
    const int hh = bh & 3;
    const int i  = threadIdx.x;
    if (i >= CH) return;

    float a[CH];
    const float nq = fmaxf(sqrtf(g_norm[bh * 96 + i]), 1e-12f);
    const float tmp = temperature[hh];
    for (int j = 0; j < CH; ++j) {
        const float nk = fmaxf(sqrtf(g_norm[bh * 96 + 48 + j]), 1e-12f);
        a[j] = g_S[bh * CH * CH + i * CH + j] * tmp / (nq * nk);
    }

    // rank with index-order tiebreak (matches jax.lax.top_k)
    int rank[CH];
    for (int j = 0; j < CH; ++j) {
        int r = 0;
        for (int l = 0; l < CH; ++l)
            if (a[l] > a[j] || (a[l] == a[j] && l < j)) r++;
        rank[j] = r;
    }

    float comb[CH];
    for (int j = 0; j < CH; ++j) comb[j] = 0.f;

    const int kvals[4] = {24, 32, 36, 38};
    for (int r = 0; r < 4; ++r) {
        const int kv = kvals[r];
        float m = -INFINITY;
        for (int j = 0; j < CH; ++j)
            if (rank[j] < kv) m = fmaxf(m, a[j]);
        float e[CH];
        float ssum = 0.f;
        for (int j = 0; j < CH; ++j) {
            e[j] = (rank[j] < kv) ? expf(a[j] - m) : 0.f;
            ssum += e[j];
        }
        const float wgt = attn_w[r] / ssum;
        for (int j = 0; j < CH; ++j) comb[j] = fmaf(e[j], wgt, comb[j]);
    }

    for (int j = 0; j < CH; ++j)
        g_comb[bh * CH * CH + i * CH + j] = comb[j];
}

// ---------------- out = comb @ v -------------------------------------------
// grid (16 bh, 64 tiles of 256 n), 256 threads; each thread handles one n.
// Dot products packed pairwise along d (f32x2).
__global__ __launch_bounds__(256) void attn_apply()
{
    const int bh = blockIdx.x;
    const int b  = bh >> 2;
    const int hh = bh & 3;

    __shared__ __align__(16) float cs[CH][CH];   // row stride 192B, 8B aligned
    const int tid = threadIdx.x;
    for (int l = tid; l < CH * CH; l += 256)
        cs[l / CH][l % CH] = g_comb[bh * CH * CH + l];
    __syncthreads();

    const int n = blockIdx.y * 256 + tid;
    const float* vb = g_dw + ((size_t)b * MQKV + 2 * DIM + hh * CH) * HW + n;
    u64 v2[CH / 2];
    #pragma unroll
    for (int d2 = 0; d2 < CH / 2; ++d2) {
        const float vl = vb[(size_t)(2 * d2) * HW];
        const float vh = vb[(size_t)(2 * d2 + 1) * HW];
        u64 p;
        asm("mov.b64 %0, {%1, %2};" : "=l"(p)
            : "r"(__float_as_uint(vl)), "r"(__float_as_uint(vh)));
        v2[d2] = p;
    }

    float* ob = g_ao + ((size_t)b * DIM + hh * CH) * HW + n;
    #pragma unroll 4
    for (int c = 0; c < CH; ++c) {
        u64 s2 = 0ull;
        #pragma unroll
        for (int d2 = 0; d2 < CH / 2; ++d2)
            ffma2(s2, *(const u64*)&cs[c][2 * d2], v2[d2]);
        ob[(size_t)c * HW] = hsum2(s2);
    }
}

// ---------------- launch ----------------------------------------------------
extern "C" void kernel_launch(void* const* d_in, const int* in_sizes, int n_in,
                              void* d_out, int out_size)
{
    const float* x           = (const float*)d_in[0];  // [4,192,128,128]
    const float* w_qkv       = (const float*)d_in[1];  // [576,192]
    const float* w_dw        = (const float*)d_in[2];  // [576,9]
    const float* w_proj      = (const float*)d_in[3];  // [192,192]
    const float* temperature = (const float*)d_in[4];  // [4]
    const float* attn_w      = (const float*)d_in[5];  // [4]
    float* out = (float*)d_out;

    float* qkv; cudaGetSymbolAddress((void**)&qkv, g_qkv);
    float* dw;  cudaGetSymbolAddress((void**)&dw,  g_dw);
    float* ao;  cudaGetSymbolAddress((void**)&ao,  g_ao);

    // 1. qkv = w_qkv @ x   (per batch GEMM 576 x 16384 x 192)
    gemm_conv1x1<<<dim3(HW / BN, (MQKV + BM - 1) / BM, BATCH), 256>>>(
        w_qkv, x, qkv, MQKV);

    // 2. depthwise 3x3
    dwconv3x3<<<dim3(HH, BATCH * MQKV), 128>>>(qkv, w_dw, dw);

    // 3. zero accumulators, then attn partials (S, norms)
    zero_small<<<(BHN * CH * CH + 255) / 256, 256>>>();
    attn_partial<<<dim3(BHN, 64), 256>>>();

    // 4. finalize combined attention weights (topk + softmax + weighted sum)
    finalize_comb<<<BHN, 64>>>(temperature, attn_w);

    // 5. out = comb @ v
    attn_apply<<<dim3(BHN, HW / 256), 256>>>();

    // 6. projection conv1x1 -> d_out
    gemm_conv1x1<<<dim3(HW / BN, (DIM + BM - 1) / BM, BATCH), 256>>>(
        w_proj, ao, out, DIM);
}

// round 7
// speedup vs baseline: 1.4455x; 1.3399x over previous
#include <cuda_runtime.h>
#include <cuda_bf16.h>
#include <math.h>
#include <stdint.h>

// Problem constants
#define BATCH  4
#define DIM    192
#define HH     128
#define WW     128
#define HW     16384            // 128*128
#define HEADS  4
#define CH     48               // DIM / HEADS
#define MQKV   576              // 3*DIM
#define KDIM   192              // reduction dim of 1x1 convs
#define BHN    16               // BATCH*HEADS

typedef unsigned long long u64;

// ---------------- packed f32x2 helpers (attn kernels) ----------------------
__device__ __forceinline__ void ffma2(u64& d, u64 a, u64 b) {
    asm("fma.rn.f32x2 %0, %1, %2, %0;" : "+l"(d) : "l"(a), "l"(b));
}
__device__ __forceinline__ float lo2(u64 v) {
    return __uint_as_float((unsigned)(v & 0xffffffffull));
}
__device__ __forceinline__ float hi2(u64 v) {
    return __uint_as_float((unsigned)(v >> 32));
}
__device__ __forceinline__ float hsum2(u64 v) { return lo2(v) + hi2(v); }

// ---------------- warp-MMA helpers (baseline ISA, no arch suffix) ----------
__device__ __forceinline__ uint32_t smem_u32(const void* p) {
    uint32_t a;
    asm("{ .reg .u64 t; cvta.to.shared.u64 t, %1; cvt.u32.u64 %0, t; }"
        : "=r"(a) : "l"(p));
    return a;
}
__device__ __forceinline__ void ldm_x4(uint32_t r[4], uint32_t addr) {
    asm volatile("ldmatrix.sync.aligned.m8n8.x4.shared.b16 {%0,%1,%2,%3}, [%4];"
                 : "=r"(r[0]), "=r"(r[1]), "=r"(r[2]), "=r"(r[3]) : "r"(addr));
}
__device__ __forceinline__ void ldm_x2t(uint32_t r[2], uint32_t addr) {
    asm volatile("ldmatrix.sync.aligned.m8n8.x2.trans.shared.b16 {%0,%1}, [%2];"
                 : "=r"(r[0]), "=r"(r[1]) : "r"(addr));
}
__device__ __forceinline__ void mma_bf16(float c[4], const uint32_t a[4],
                                         const uint32_t b[2]) {
    asm volatile(
        "mma.sync.aligned.m16n8k16.row.col.f32.bf16.bf16.f32 "
        "{%0,%1,%2,%3}, {%4,%5,%6,%7}, {%8,%9}, {%0,%1,%2,%3};"
        : "+f"(c[0]), "+f"(c[1]), "+f"(c[2]), "+f"(c[3])
        : "r"(a[0]), "r"(a[1]), "r"(a[2]), "r"(a[3]), "r"(b[0]), "r"(b[1]));
}

// ---------------- scratch (device globals; no allocation allowed) ----------
__device__ __align__(16) float g_qkv[(size_t)BATCH * MQKV * HW];  // conv1x1 qkv output
__device__ __align__(16) float g_dw [(size_t)BATCH * MQKV * HW];  // after depthwise 3x3
__device__ __align__(16) float g_S   [BHN * CH * CH];             // raw q.k^T partial sums
__device__ __align__(16) float g_norm[BHN * 96];                  // sumsq: q rows then k rows
__device__ __align__(16) float g_comb[BHN * CH * CH];             // combined attention weights
__device__ __align__(16) float g_ao  [(size_t)BATCH * DIM * HW];  // comb @ v
// bf16 hi/lo split weights
__device__ __align__(16) __nv_bfloat16 g_wqh[MQKV * KDIM];
__device__ __align__(16) __nv_bfloat16 g_wql[MQKV * KDIM];
__device__ __align__(16) __nv_bfloat16 g_wph[DIM * KDIM];
__device__ __align__(16) __nv_bfloat16 g_wpl[DIM * KDIM];

// ---------------- weight split: fp32 -> bf16 hi + bf16 lo ------------------
__global__ void w_split(const float* __restrict__ wq, const float* __restrict__ wp)
{
    const int i = blockIdx.x * 256 + threadIdx.x;
    if (i < MQKV * KDIM) {
        const float x = wq[i];
        const __nv_bfloat16 h = __float2bfloat16(x);
        g_wqh[i] = h;
        g_wql[i] = __float2bfloat16(x - __bfloat162float(h));
    }
    if (i < DIM * KDIM) {
        const float x = wp[i];
        const __nv_bfloat16 h = __float2bfloat16(x);
        g_wph[i] = h;
        g_wpl[i] = __float2bfloat16(x - __bfloat162float(h));
    }
}

// ---------------- tensor-core conv1x1 via mma.sync bf16 3-product split ----
// Y[b][m][p] = sum_k W[m][k] X[b][k][p].  Block: 128(M) x 128(N=p), 8 warps
// (2x4), warp tile 64x32, K-tile 48 (3 k16 steps), K=192 -> 4 tiles.
// smem: A [m][k] stride 56 bf16 (112B) conflict-free for ldmatrix.x4;
//       B [k][n] stride 136 bf16 (272B) conflict-free for ldmatrix.x2.trans.
#define GA_STRIDE 56
#define GB_STRIDE 136
#define GS_AH 0
#define GS_AL (128 * GA_STRIDE)                 // bf16 idx
#define GS_BH (2 * 128 * GA_STRIDE)
#define GS_BL (2 * 128 * GA_STRIDE + 48 * GB_STRIDE)
#define G_SMEM_BF16 (2 * 128 * GA_STRIDE + 2 * 48 * GB_STRIDE)
#define G_SMEM_BYTES (G_SMEM_BF16 * 2)          // 54784

__global__ __launch_bounds__(256) void gemm_mma(
    const __nv_bfloat16* __restrict__ Wh, const __nv_bfloat16* __restrict__ Wl,
    const float* __restrict__ X, float* __restrict__ Y, int M)
{
    extern __shared__ __align__(16) __nv_bfloat16 sm[];
    __nv_bfloat16* sAh = sm + GS_AH;
    __nv_bfloat16* sAl = sm + GS_AL;
    __nv_bfloat16* sBh = sm + GS_BH;
    __nv_bfloat16* sBl = sm + GS_BL;
    const uint32_t uAh = smem_u32(sAh), uAl = smem_u32(sAl);
    const uint32_t uBh = smem_u32(sBh), uBl = smem_u32(sBl);

    const int tid  = threadIdx.x;
    const int lane = tid & 31;
    const int wid  = tid >> 5;
    const int wm   = (wid >> 2) * 64;     // warp m offset
    const int wn   = (wid & 3) * 32;      // warp n offset
    const int b    = blockIdx.z;
    const int m0   = blockIdx.y * 128;
    const int p0   = blockIdx.x * 128;
    const float* Xb = X + (size_t)b * KDIM * HW;
    float*       Yb = Y + (size_t)b * M * HW;

    float acc[4][4][4];
    #pragma unroll
    for (int mi = 0; mi < 4; ++mi)
        #pragma unroll
        for (int ni = 0; ni < 4; ++ni)
            #pragma unroll
            for (int r = 0; r < 4; ++r) acc[mi][ni][r] = 0.f;

    for (int kt = 0; kt < 4; ++kt) {
        const int k0 = kt * 48;
        // ---- A tile: pre-split bf16 weights, rows m0..m0+127, k0..k0+47 ----
        #pragma unroll
        for (int i = 0; i < 6; ++i) {                 // 1536 u64 chunks
            const int c   = tid + 256 * i;
            const int row = c / 12;
            const int cc  = c % 12;
            const int m   = m0 + row;
            u64 vh = 0ull, vl = 0ull;
            if (m < M) {
                vh = *(const u64*)(Wh + (size_t)m * KDIM + k0 + cc * 4);
                vl = *(const u64*)(Wl + (size_t)m * KDIM + k0 + cc * 4);
            }
            *(u64*)(sAh + row * GA_STRIDE + cc * 4) = vh;
            *(u64*)(sAl + row * GA_STRIDE + cc * 4) = vl;
        }
        // ---- B tile: X fp32 -> bf16 hi/lo, stored [k][n] (no transpose) ----
        #pragma unroll
        for (int i = 0; i < 6; ++i) {                 // 48 rows x 32 float4
            const int c  = tid + 256 * i;
            const int kk = c >> 5;
            const int p4 = (c & 31) * 4;
            const float4 v = *(const float4*)(Xb + (size_t)(k0 + kk) * HW + p0 + p4);
            __nv_bfloat16 h[4], l[4];
            h[0] = __float2bfloat16(v.x); l[0] = __float2bfloat16(v.x - __bfloat162float(h[0]));
            h[1] = __float2bfloat16(v.y); l[1] = __float2bfloat16(v.y - __bfloat162float(h[1]));
            h[2] = __float2bfloat16(v.z); l[2] = __float2bfloat16(v.z - __bfloat162float(h[2]));
            h[3] = __float2bfloat16(v.w); l[3] = __float2bfloat16(v.w - __bfloat162float(h[3]));
            *(u64*)(sBh + kk * GB_STRIDE + p4) = *(const u64*)h;
            *(u64*)(sBl + kk * GB_STRIDE + p4) = *(const u64*)l;
        }
        __syncthreads();

        #pragma unroll
        for (int ks = 0; ks < 3; ++ks) {
            const int kk0 = ks * 16;
            // B fragments (k16 x n8 each), hi and lo
            uint32_t bh[4][2], bl[4][2];
            const int brow = kk0 + (lane & 15);
            #pragma unroll
            for (int ni = 0; ni < 4; ++ni) {
                const uint32_t boffB = (uint32_t)(brow * GB_STRIDE + wn + ni * 8) * 2;
                ldm_x2t(bh[ni], uBh + boffB);
                ldm_x2t(bl[ni], uBl + boffB);
            }
            const int arow = wm + (lane & 15);
            const uint32_t akcol = (uint32_t)(kk0 + ((lane >> 4) << 3));
            #pragma unroll
            for (int mi = 0; mi < 4; ++mi) {
                uint32_t ah[4], al[4];
                const uint32_t aoff = (uint32_t)((arow + mi * 16) * GA_STRIDE + akcol) * 2;
                ldm_x4(ah, uAh + aoff);
                ldm_x4(al, uAl + aoff);
                #pragma unroll
                for (int ni = 0; ni < 4; ++ni) {
                    mma_bf16(acc[mi][ni], ah, bh[ni]);   // Ah*Bh
                    mma_bf16(acc[mi][ni], ah, bl[ni]);   // Ah*Bl
                    mma_bf16(acc[mi][ni], al, bh[ni]);   // Al*Bh
                }
            }
        }
        __syncthreads();
    }

    // ---- epilogue: C frag (m16n8): c0,c1 = (g, 2tg..+1), c2,c3 = (g+8, ..)
    const int g  = lane >> 2;
    const int tg = lane & 3;
    #pragma unroll
    for (int mi = 0; mi < 4; ++mi) {
        #pragma unroll
        for (int ni = 0; ni < 4; ++ni) {
            const int m = m0 + wm + mi * 16 + g;
            const int p = p0 + wn + ni * 8 + tg * 2;
            if (m < M)
                *(float2*)(Yb + (size_t)m * HW + p) =
                    make_float2(acc[mi][ni][0], acc[mi][ni][1]);
            if (m + 8 < M)
                *(float2*)(Yb + (size_t)(m + 8) * HW + p) =
                    make_float2(acc[mi][ni][2], acc[mi][ni][3]);
        }
    }
}

// ---------------- depthwise 3x3, pad 1 -------------------------------------
__global__ __launch_bounds__(128) void dwconv3x3(
    const float* __restrict__ in, const float* __restrict__ wdw,
    float* __restrict__ out)
{
    const int h  = blockIdx.x;          // 0..127
    const int bc = blockIdx.y;          // 0..BATCH*MQKV-1
    const int w  = threadIdx.x;         // 0..127
    const int ch = bc % MQKV;
    const float* wp   = wdw + ch * 9;
    const float* base = in + (size_t)bc * HW;

    float s = 0.f;
    #pragma unroll
    for (int dy = -1; dy <= 1; ++dy) {
        const int hh = h + dy;
        if (hh < 0 || hh >= HH) continue;
        #pragma unroll
        for (int dx = -1; dx <= 1; ++dx) {
            const int ww = w + dx;
            if (ww < 0 || ww >= WW) continue;
            s = fmaf(base[hh * WW + ww], wp[(dy + 1) * 3 + (dx + 1)], s);
        }
    }
    out[(size_t)bc * HW + h * WW + w] = s;
}

// ---------------- zero the accumulation buffers ----------------------------
__global__ void zero_small()
{
    const int i = blockIdx.x * 256 + threadIdx.x;
    if (i < BHN * CH * CH) g_S[i] = 0.f;
    if (i < BHN * 96)      g_norm[i] = 0.f;
}

// ---------------- attn partials: S = q k^T, plus row sumsq -----------------
__global__ __launch_bounds__(256) void attn_partial()
{
    const int bh  = blockIdx.x;
    const int seg = blockIdx.y;
    const int b   = bh >> 2;
    const int hh  = bh & 3;
    const float* qbase = g_dw + ((size_t)b * MQKV + hh * CH) * HW;
    const float* kbase = g_dw + ((size_t)b * MQKV + DIM + hh * CH) * HW;
    const int n0 = seg * 256;

    __shared__ __align__(16) float qs[48][68];   // stride 272B (16B multiple)
    __shared__ __align__(16) float ks[48][68];

    const int tid = threadIdx.x;
    const int i0  = (tid >> 4) * 3;
    const int j0  = (tid & 15) * 3;

    u64 acc2[3][3];
    #pragma unroll
    for (int i = 0; i < 3; ++i)
        #pragma unroll
        for (int j = 0; j < 3; ++j) acc2[i][j] = 0ull;
    u64 sq2 = 0ull;

    for (int c = 0; c < 4; ++c) {
        const int nb = n0 + c * 64;
        for (int l = tid; l < 48 * 16; l += 256) {   // float4 granules
            const int row  = l >> 4;
            const int col4 = (l & 15) << 2;
            *(float4*)&qs[row][col4] =
                *(const float4*)(qbase + (size_t)row * HW + nb + col4);
            *(float4*)&ks[row][col4] =
                *(const float4*)(kbase + (size_t)row * HW + nb + col4);
        }
        __syncthreads();
        #pragma unroll 4
        for (int t = 0; t < 64; t += 2) {
            u64 qa[3], kb[3];
            #pragma unroll
            for (int i = 0; i < 3; ++i) qa[i] = *(const u64*)&qs[i0 + i][t];
            #pragma unroll
            for (int j = 0; j < 3; ++j) kb[j] = *(const u64*)&ks[j0 + j][t];
            #pragma unroll
            for (int i = 0; i < 3; ++i)
                #pragma unroll
                for (int j = 0; j < 3; ++j)
                    ffma2(acc2[i][j], qa[i], kb[j]);
            if (tid < 96) {
                const u64 v = (tid < 48) ? *(const u64*)&qs[tid][t]
                                         : *(const u64*)&ks[tid - 48][t];
                ffma2(sq2, v, v);
            }
        }
        __syncthreads();
    }

    float* Sp = g_S + bh * CH * CH;
    #pragma unroll
    for (int i = 0; i < 3; ++i)
        #pragma unroll
        for (int j = 0; j < 3; ++j)
            atomicAdd(&Sp[(i0 + i) * CH + (j0 + j)], hsum2(acc2[i][j]));
    if (tid < 96) atomicAdd(&g_norm[bh * 96 + tid], hsum2(sq2));
}

// ---------------- finalize: normalize, per-row topk/softmax, combine -------
// k values: int(48*rate) in IEEE double: {24, 32 (round-to-even), 36, 38}
__global__ void finalize_comb(const float* __restrict__ temperature,
                              const float* __restrict__ attn_w)
{
    const int bh = blockIdx.x;
    const int hh = bh & 3;
    const int i  = threadIdx.x;
    if (i >= CH) return;

    float a[CH];
    const float nq = fmaxf(sqrtf(g_norm[bh * 96 + i]), 1e-12f);
    const float tmp = temperature[hh];
    for (int j = 0; j < CH; ++j) {
        const float nk = fmaxf(sqrtf(g_norm[bh * 96 + 48 + j]), 1e-12f);
        a[j] = g_S[bh * CH * CH + i * CH + j] * tmp / (nq * nk);
    }

    int rank[CH];
    for (int j = 0; j < CH; ++j) {
        int r = 0;
        for (int l = 0; l < CH; ++l)
            if (a[l] > a[j] || (a[l] == a[j] && l < j)) r++;
        rank[j] = r;
    }

    float comb[CH];
    for (int j = 0; j < CH; ++j) comb[j] = 0.f;

    const int kvals[4] = {24, 32, 36, 38};
    for (int r = 0; r < 4; ++r) {
        const int kv = kvals[r];
        float m = -INFINITY;
        for (int j = 0; j < CH; ++j)
            if (rank[j] < kv) m = fmaxf(m, a[j]);
        float e[CH];
        float ssum = 0.f;
        for (int j = 0; j < CH; ++j) {
            e[j] = (rank[j] < kv) ? expf(a[j] - m) : 0.f;
            ssum += e[j];
        }
        const float wgt = attn_w[r] / ssum;
        for (int j = 0; j < CH; ++j) comb[j] = fmaf(e[j], wgt, comb[j]);
    }

    for (int j = 0; j < CH; ++j)
        g_comb[bh * CH * CH + i * CH + j] = comb[j];
}

// ---------------- out = comb @ v -------------------------------------------
__global__ __launch_bounds__(256) void attn_apply()
{
    const int bh = blockIdx.x;
    const int b  = bh >> 2;
    const int hh = bh & 3;

    __shared__ __align__(16) float cs[CH][CH];
    const int tid = threadIdx.x;
    for (int l = tid; l < CH * CH; l += 256)
        cs[l / CH][l % CH] = g_comb[bh * CH * CH + l];
    __syncthreads();

    const int n = blockIdx.y * 256 + tid;
    const float* vb = g_dw + ((size_t)b * MQKV + 2 * DIM + hh * CH) * HW + n;
    u64 v2[CH / 2];
    #pragma unroll
    for (int d2 = 0; d2 < CH / 2; ++d2) {
        const float vl = vb[(size_t)(2 * d2) * HW];
        const float vh = vb[(size_t)(2 * d2 + 1) * HW];
        u64 pk;
        asm("mov.b64 %0, {%1, %2};" : "=l"(pk)
            : "r"(__float_as_uint(vl)), "r"(__float_as_uint(vh)));
        v2[d2] = pk;
    }

    float* ob = g_ao + ((size_t)b * DIM + hh * CH) * HW + n;
    #pragma unroll 4
    for (int c = 0; c < CH; ++c) {
        u64 s2 = 0ull;
        #pragma unroll
        for (int d2 = 0; d2 < CH / 2; ++d2)
            ffma2(s2, *(const u64*)&cs[c][2 * d2], v2[d2]);
        ob[(size_t)c * HW] = hsum2(s2);
    }
}

// ---------------- launch ----------------------------------------------------
extern "C" void kernel_launch(void* const* d_in, const int* in_sizes, int n_in,
                              void* d_out, int out_size)
{
    const float* x           = (const float*)d_in[0];  // [4,192,128,128]
    const float* w_qkv       = (const float*)d_in[1];  // [576,192]
    const float* w_dw        = (const float*)d_in[2];  // [576,9]
    const float* w_proj      = (const float*)d_in[3];  // [192,192]
    const float* temperature = (const float*)d_in[4];  // [4]
    const float* attn_w      = (const float*)d_in[5];  // [4]
    float* out = (float*)d_out;

    float* qkv; cudaGetSymbolAddress((void**)&qkv, g_qkv);
    float* dw;  cudaGetSymbolAddress((void**)&dw,  g_dw);
    float* ao;  cudaGetSymbolAddress((void**)&ao,  g_ao);
    __nv_bfloat16* wqh; cudaGetSymbolAddress((void**)&wqh, g_wqh);
    __nv_bfloat16* wql; cudaGetSymbolAddress((void**)&wql, g_wql);
    __nv_bfloat16* wph; cudaGetSymbolAddress((void**)&wph, g_wph);
    __nv_bfloat16* wpl; cudaGetSymbolAddress((void**)&wpl, g_wpl);

    static bool attr_set = false;
    if (!attr_set) {
        cudaFuncSetAttribute(gemm_mma,
                             cudaFuncAttributeMaxDynamicSharedMemorySize,
                             G_SMEM_BYTES);
        attr_set = true;
    }

    // 0. split weights into bf16 hi/lo
    w_split<<<(MQKV * KDIM + 255) / 256, 256>>>(w_qkv, w_proj);

    // 1. qkv = w_qkv @ x  (tensor cores via mma.sync, 3-product bf16 split)
    gemm_mma<<<dim3(HW / 128, (MQKV + 127) / 128, BATCH), 256, G_SMEM_BYTES>>>(
        wqh, wql, x, qkv, MQKV);

    // 2. depthwise 3x3
    dwconv3x3<<<dim3(HH, BATCH * MQKV), 128>>>(qkv, w_dw, dw);

    // 3. zero accumulators, then attn partials (S, norms)
    zero_small<<<(BHN * CH * CH + 255) / 256, 256>>>();
    attn_partial<<<dim3(BHN, 64), 256>>>();

    // 4. finalize combined attention weights (topk + softmax + weighted sum)
    finalize_comb<<<BHN, 64>>>(temperature, attn_w);

    // 5. out = comb @ v
    attn_apply<<<dim3(BHN, HW / 256), 256>>>();

    // 6. projection conv1x1 -> d_out (tensor cores)
    gemm_mma<<<dim3(HW / 128, (DIM + 127) / 128, BATCH), 256, G_SMEM_BYTES>>>(
        wph, wpl, ao, out, DIM);
}

// round 8
// speedup vs baseline: 1.7302x; 1.1969x over previous
#include <cuda_runtime.h>
#include <cuda_bf16.h>
#include <math.h>
#include <stdint.h>

// Problem constants
#define BATCH  4
#define DIM    192
#define HH     128
#define WW     128
#define HW     16384            // 128*128
#define HEADS  4
#define CH     48               // DIM / HEADS
#define MQKV   576              // 3*DIM
#define KDIM   192              // reduction dim of 1x1 convs
#define BHN    16               // BATCH*HEADS

typedef unsigned long long u64;

// ---------------- packed f32x2 helpers (attn kernels) ----------------------
__device__ __forceinline__ void ffma2(u64& d, u64 a, u64 b) {
    asm("fma.rn.f32x2 %0, %1, %2, %0;" : "+l"(d) : "l"(a), "l"(b));
}
__device__ __forceinline__ float lo2(u64 v) {
    return __uint_as_float((unsigned)(v & 0xffffffffull));
}
__device__ __forceinline__ float hi2(u64 v) {
    return __uint_as_float((unsigned)(v >> 32));
}
__device__ __forceinline__ float hsum2(u64 v) { return lo2(v) + hi2(v); }

// ---------------- warp-MMA helpers (baseline ISA, no arch suffix) ----------
__device__ __forceinline__ uint32_t smem_u32(const void* p) {
    uint32_t a;
    asm("{ .reg .u64 t; cvta.to.shared.u64 t, %1; cvt.u32.u64 %0, t; }"
        : "=r"(a) : "l"(p));
    return a;
}
__device__ __forceinline__ void ldm_x4(uint32_t r[4], uint32_t addr) {
    asm volatile("ldmatrix.sync.aligned.m8n8.x4.shared.b16 {%0,%1,%2,%3}, [%4];"
                 : "=r"(r[0]), "=r"(r[1]), "=r"(r[2]), "=r"(r[3]) : "r"(addr));
}
__device__ __forceinline__ void ldm_x2t(uint32_t r[2], uint32_t addr) {
    asm volatile("ldmatrix.sync.aligned.m8n8.x2.trans.shared.b16 {%0,%1}, [%2];"
                 : "=r"(r[0]), "=r"(r[1]) : "r"(addr));
}
__device__ __forceinline__ void mma_bf16(float c[4], const uint32_t a[4],
                                         const uint32_t b[2]) {
    asm volatile(
        "mma.sync.aligned.m16n8k16.row.col.f32.bf16.bf16.f32 "
        "{%0,%1,%2,%3}, {%4,%5,%6,%7}, {%8,%9}, {%0,%1,%2,%3};"
        : "+f"(c[0]), "+f"(c[1]), "+f"(c[2]), "+f"(c[3])
        : "r"(a[0]), "r"(a[1]), "r"(a[2]), "r"(a[3]), "r"(b[0]), "r"(b[1]));
}

// ---------------- scratch (device globals; no allocation allowed) ----------
__device__ __align__(16) float g_qkv[(size_t)BATCH * MQKV * HW];  // conv1x1 qkv output
__device__ __align__(16) float g_dw [(size_t)BATCH * MQKV * HW];  // after depthwise 3x3
__device__ __align__(16) float g_S   [BHN * CH * CH];             // raw q.k^T partial sums
__device__ __align__(16) float g_norm[BHN * 96];                  // sumsq: q rows then k rows
__device__ __align__(16) float g_comb[BHN * CH * CH];             // combined attention weights
// bf16 hi/lo split weights
__device__ __align__(16) __nv_bfloat16 g_wqh[MQKV * KDIM];
__device__ __align__(16) __nv_bfloat16 g_wql[MQKV * KDIM];
__device__ __align__(16) __nv_bfloat16 g_weh[BATCH * DIM * KDIM]; // W_eff hi (per batch)
__device__ __align__(16) __nv_bfloat16 g_wel[BATCH * DIM * KDIM]; // W_eff lo

// ---------------- weight split + zero accumulators (one launch) ------------
__global__ void w_split(const float* __restrict__ wq)
{
    const int i = blockIdx.x * 256 + threadIdx.x;
    if (i < MQKV * KDIM) {
        const float x = wq[i];
        const __nv_bfloat16 h = __float2bfloat16(x);
        g_wqh[i] = h;
        g_wql[i] = __float2bfloat16(x - __bfloat162float(h));
    }
    if (i < BHN * CH * CH) g_S[i] = 0.f;
    if (i < BHN * 96)      g_norm[i] = 0.f;
}

// ---------------- tensor-core conv1x1 via mma.sync bf16 3-product split ----
// Y[b][m][p] = sum_k W_b[m][k] X_b[k][p].  Block: 128(M) x 128(N=p), 8 warps
// (2x4), warp tile 64x32, K-tile 48 (3 k16 steps), K=192 -> 4 tiles.
// Per-batch strides: weights advance wstride elems / batch, X xstride.
#define GA_STRIDE 56
#define GB_STRIDE 136
#define GS_AH 0
#define GS_AL (128 * GA_STRIDE)                 // bf16 idx
#define GS_BH (2 * 128 * GA_STRIDE)
#define GS_BL (2 * 128 * GA_STRIDE + 48 * GB_STRIDE)
#define G_SMEM_BF16 (2 * 128 * GA_STRIDE + 2 * 48 * GB_STRIDE)
#define G_SMEM_BYTES (G_SMEM_BF16 * 2)          // 54784

__global__ __launch_bounds__(256) void gemm_mma(
    const __nv_bfloat16* __restrict__ Wh, const __nv_bfloat16* __restrict__ Wl,
    const float* __restrict__ X, float* __restrict__ Y, int M,
    long wstride, long xstride, long ystride)
{
    extern __shared__ __align__(16) __nv_bfloat16 sm[];
    __nv_bfloat16* sAh = sm + GS_AH;
    __nv_bfloat16* sAl = sm + GS_AL;
    __nv_bfloat16* sBh = sm + GS_BH;
    __nv_bfloat16* sBl = sm + GS_BL;
    const uint32_t uAh = smem_u32(sAh), uAl = smem_u32(sAl);
    const uint32_t uBh = smem_u32(sBh), uBl = smem_u32(sBl);

    const int tid  = threadIdx.x;
    const int lane = tid & 31;
    const int wid  = tid >> 5;
    const int wm   = (wid >> 2) * 64;     // warp m offset
    const int wn   = (wid & 3) * 32;      // warp n offset
    const int b    = blockIdx.z;
    const int m0   = blockIdx.y * 128;
    const int p0   = blockIdx.x * 128;
    const __nv_bfloat16* Whb = Wh + (size_t)b * wstride;
    const __nv_bfloat16* Wlb = Wl + (size_t)b * wstride;
    const float* Xb = X + (size_t)b * xstride;
    float*       Yb = Y + (size_t)b * ystride;

    float acc[4][4][4];
    #pragma unroll
    for (int mi = 0; mi < 4; ++mi)
        #pragma unroll
        for (int ni = 0; ni < 4; ++ni)
            #pragma unroll
            for (int r = 0; r < 4; ++r) acc[mi][ni][r] = 0.f;

    for (int kt = 0; kt < 4; ++kt) {
        const int k0 = kt * 48;
        // ---- A tile: pre-split bf16 weights, rows m0..m0+127, k0..k0+47 ----
        #pragma unroll
        for (int i = 0; i < 6; ++i) {                 // 1536 u64 chunks
            const int c   = tid + 256 * i;
            const int row = c / 12;
            const int cc  = c % 12;
            const int m   = m0 + row;
            u64 vh = 0ull, vl = 0ull;
            if (m < M) {
                vh = *(const u64*)(Whb + (size_t)m * KDIM + k0 + cc * 4);
                vl = *(const u64*)(Wlb + (size_t)m * KDIM + k0 + cc * 4);
            }
            *(u64*)(sAh + row * GA_STRIDE + cc * 4) = vh;
            *(u64*)(sAl + row * GA_STRIDE + cc * 4) = vl;
        }
        // ---- B tile: X fp32 -> bf16 hi/lo, stored [k][n] (no transpose) ----
        #pragma unroll
        for (int i = 0; i < 6; ++i) {                 // 48 rows x 32 float4
            const int c  = tid + 256 * i;
            const int kk = c >> 5;
            const int p4 = (c & 31) * 4;
            const float4 v = *(const float4*)(Xb + (size_t)(k0 + kk) * HW + p0 + p4);
            __nv_bfloat16 h[4], l[4];
            h[0] = __float2bfloat16(v.x); l[0] = __float2bfloat16(v.x - __bfloat162float(h[0]));
            h[1] = __float2bfloat16(v.y); l[1] = __float2bfloat16(v.y - __bfloat162float(h[1]));
            h[2] = __float2bfloat16(v.z); l[2] = __float2bfloat16(v.z - __bfloat162float(h[2]));
            h[3] = __float2bfloat16(v.w); l[3] = __float2bfloat16(v.w - __bfloat162float(h[3]));
            *(u64*)(sBh + kk * GB_STRIDE + p4) = *(const u64*)h;
            *(u64*)(sBl + kk * GB_STRIDE + p4) = *(const u64*)l;
        }
        __syncthreads();

        #pragma unroll
        for (int ks = 0; ks < 3; ++ks) {
            const int kk0 = ks * 16;
            uint32_t bh[4][2], bl[4][2];
            const int brow = kk0 + (lane & 15);
            #pragma unroll
            for (int ni = 0; ni < 4; ++ni) {
                const uint32_t boffB = (uint32_t)(brow * GB_STRIDE + wn + ni * 8) * 2;
                ldm_x2t(bh[ni], uBh + boffB);
                ldm_x2t(bl[ni], uBl + boffB);
            }
            const int arow = wm + (lane & 15);
            const uint32_t akcol = (uint32_t)(kk0 + ((lane >> 4) << 3));
            #pragma unroll
            for (int mi = 0; mi < 4; ++mi) {
                uint32_t ah[4], al[4];
                const uint32_t aoff = (uint32_t)((arow + mi * 16) * GA_STRIDE + akcol) * 2;
                ldm_x4(ah, uAh + aoff);
                ldm_x4(al, uAl + aoff);
                #pragma unroll
                for (int ni = 0; ni < 4; ++ni) {
                    mma_bf16(acc[mi][ni], ah, bh[ni]);   // Ah*Bh
                    mma_bf16(acc[mi][ni], ah, bl[ni]);   // Ah*Bl
                    mma_bf16(acc[mi][ni], al, bh[ni]);   // Al*Bh
                }
            }
        }
        __syncthreads();
    }

    const int g  = lane >> 2;
    const int tg = lane & 3;
    #pragma unroll
    for (int mi = 0; mi < 4; ++mi) {
        #pragma unroll
        for (int ni = 0; ni < 4; ++ni) {
            const int m = m0 + wm + mi * 16 + g;
            const int p = p0 + wn + ni * 8 + tg * 2;
            if (m < M)
                *(float2*)(Yb + (size_t)m * HW + p) =
                    make_float2(acc[mi][ni][0], acc[mi][ni][1]);
            if (m + 8 < M)
                *(float2*)(Yb + (size_t)(m + 8) * HW + p) =
                    make_float2(acc[mi][ni][2], acc[mi][ni][3]);
        }
    }
}

// ---------------- depthwise 3x3, pad 1, smem-tiled 128x16 ------------------
#define DW_TH 16
__global__ __launch_bounds__(256) void dwconv3x3_t(
    const float* __restrict__ in, const float* __restrict__ wdw,
    float* __restrict__ out)
{
    const int bc = blockIdx.y;                  // 0..BATCH*MQKV-1
    const int h0 = blockIdx.x * DW_TH;
    const int ch = bc % MQKV;
    const float* base = in + (size_t)bc * HW;
    const int tid = threadIdx.x;

    __shared__ __align__(16) float st[DW_TH + 2][132];
    __shared__ float wsh[9];
    if (tid < 9) wsh[tid] = wdw[ch * 9 + tid];

    // load rows h0-1 .. h0+16 (18 rows x 128 cols) via float4
    #pragma unroll
    for (int idx = tid; idx < 18 * 32; idx += 256) {
        const int r  = idx >> 5;
        const int c4 = (idx & 31) << 2;
        const int gh = h0 - 1 + r;
        float4 v = make_float4(0.f, 0.f, 0.f, 0.f);
        if (gh >= 0 && gh < HH) v = *(const float4*)(base + (size_t)gh * WW + c4);
        *(float4*)&st[r][c4] = v;
    }
    __syncthreads();

    const int w     = tid & 127;
    const int strip = tid >> 7;                 // 0 or 1
    const int hb    = strip * 8;                // local pixel rows hb..hb+7
    const bool wl = (w > 0), wr = (w < 127);
    const float w00 = wsh[0], w01 = wsh[1], w02 = wsh[2];
    const float w10 = wsh[3], w11 = wsh[4], w12 = wsh[5];
    const float w20 = wsh[6], w21 = wsh[7], w22 = wsh[8];

    float l0 = wl ? st[hb][w - 1] : 0.f;
    float m0 = st[hb][w];
    float r0 = wr ? st[hb][w + 1] : 0.f;
    float l1 = wl ? st[hb + 1][w - 1] : 0.f;
    float m1 = st[hb + 1][w];
    float r1 = wr ? st[hb + 1][w + 1] : 0.f;

    float* ob = out + (size_t)bc * HW + (size_t)(h0 + hb) * WW + w;
    #pragma unroll
    for (int rr = 0; rr < 8; ++rr) {
        const int sr = hb + rr + 2;
        const float l2 = wl ? st[sr][w - 1] : 0.f;
        const float m2 = st[sr][w];
        const float r2 = wr ? st[sr][w + 1] : 0.f;
        float s = w00 * l0;
        s = fmaf(w01, m0, s); s = fmaf(w02, r0, s);
        s = fmaf(w10, l1, s); s = fmaf(w11, m1, s); s = fmaf(w12, r1, s);
        s = fmaf(w20, l2, s); s = fmaf(w21, m2, s); s = fmaf(w22, r2, s);
        ob[(size_t)rr * WW] = s;
        l0 = l1; m0 = m1; r0 = r1;
        l1 = l2; m1 = m2; r1 = r2;
    }
}

// ---------------- attn partials: S = q k^T, plus row sumsq -----------------
__global__ __launch_bounds__(256) void attn_partial()
{
    const int bh  = blockIdx.x;
    const int seg = blockIdx.y;
    const int b   = bh >> 2;
    const int hh  = bh & 3;
    const float* qbase = g_dw + ((size_t)b * MQKV + hh * CH) * HW;
    const float* kbase = g_dw + ((size_t)b * MQKV + DIM + hh * CH) * HW;
    const int n0 = seg * 256;

    __shared__ __align__(16) float qs[48][68];   // stride 272B (16B multiple)
    __shared__ __align__(16) float ks[48][68];

    const int tid = threadIdx.x;
    const int i0  = (tid >> 4) * 3;
    const int j0  = (tid & 15) * 3;

    u64 acc2[3][3];
    #pragma unroll
    for (int i = 0; i < 3; ++i)
        #pragma unroll
        for (int j = 0; j < 3; ++j) acc2[i][j] = 0ull;
    u64 sq2 = 0ull;

    for (int c = 0; c < 4; ++c) {
        const int nb = n0 + c * 64;
        for (int l = tid; l < 48 * 16; l += 256) {   // float4 granules
            const int row  = l >> 4;
            const int col4 = (l & 15) << 2;
            *(float4*)&qs[row][col4] =
                *(const float4*)(qbase + (size_t)row * HW + nb + col4);
            *(float4*)&ks[row][col4] =
                *(const float4*)(kbase + (size_t)row * HW + nb + col4);
        }
        __syncthreads();
        #pragma unroll 4
        for (int t = 0; t < 64; t += 2) {
            u64 qa[3], kb[3];
            #pragma unroll
            for (int i = 0; i < 3; ++i) qa[i] = *(const u64*)&qs[i0 + i][t];
            #pragma unroll
            for (int j = 0; j < 3; ++j) kb[j] = *(const u64*)&ks[j0 + j][t];
            #pragma unroll
            for (int i = 0; i < 3; ++i)
                #pragma unroll
                for (int j = 0; j < 3; ++j)
                    ffma2(acc2[i][j], qa[i], kb[j]);
            if (tid < 96) {
                const u64 v = (tid < 48) ? *(const u64*)&qs[tid][t]
                                         : *(const u64*)&ks[tid - 48][t];
                ffma2(sq2, v, v);
            }
        }
        __syncthreads();
    }

    float* Sp = g_S + bh * CH * CH;
    #pragma unroll
    for (int i = 0; i < 3; ++i)
        #pragma unroll
        for (int j = 0; j < 3; ++j)
            atomicAdd(&Sp[(i0 + i) * CH + (j0 + j)], hsum2(acc2[i][j]));
    if (tid < 96) atomicAdd(&g_norm[bh * 96 + tid], hsum2(sq2));
}

// ---------------- finalize: normalize, per-row topk/softmax, combine -------
// k values: int(48*rate) in IEEE double: {24, 32 (round-to-even), 36, 38}
__global__ void finalize_comb(const float* __restrict__ temperature,
                              const float* __restrict__ attn_w)
{
    const int bh = blockIdx.x;
    const int hh = bh & 3;
    const int i  = threadIdx.x;
    if (i >= CH) return;

    float a[CH];
    const float nq = fmaxf(sqrtf(g_norm[bh * 96 + i]), 1e-12f);
    const float tmp = temperature[hh];
    for (int j = 0; j < CH; ++j) {
        const float nk = fmaxf(sqrtf(g_norm[bh * 96 + 48 + j]), 1e-12f);
        a[j] = g_S[bh * CH * CH + i * CH + j] * tmp / (nq * nk);
    }

    int rank[CH];
    for (int j = 0; j < CH; ++j) {
        int r = 0;
        for (int l = 0; l < CH; ++l)
            if (a[l] > a[j] || (a[l] == a[j] && l < j)) r++;
        rank[j] = r;
    }

    float comb[CH];
    for (int j = 0; j < CH; ++j) comb[j] = 0.f;

    const int kvals[4] = {24, 32, 36, 38};
    for (int r = 0; r < 4; ++r) {
        const int kv = kvals[r];
        float m = -INFINITY;
        for (int j = 0; j < CH; ++j)
            if (rank[j] < kv) m = fmaxf(m, a[j]);
        float e[CH];
        float ssum = 0.f;
        for (int j = 0; j < CH; ++j) {
            e[j] = (rank[j] < kv) ? expf(a[j] - m) : 0.f;
            ssum += e[j];
        }
        const float wgt = attn_w[r] / ssum;
        for (int j = 0; j < CH; ++j) comb[j] = fmaf(e[j], wgt, comb[j]);
    }

    for (int j = 0; j < CH; ++j)
        g_comb[bh * CH * CH + i * CH + j] = comb[j];
}

// ---------------- W_eff = W_proj . blockdiag(comb), split to bf16 hi/lo ----
// W_eff[b][o][h*48+d] = sum_c Wproj[o][h*48+c] * comb[b,h][c][d]
__global__ __launch_bounds__(192) void weff_compute(const float* __restrict__ wproj)
{
    const int bh = blockIdx.x;          // 0..15
    const int b  = bh >> 2;
    const int hh = bh & 3;
    const int o  = threadIdx.x;         // 0..191

    __shared__ float cs[CH][CH];
    for (int l = o; l < CH * CH; l += 192)
        cs[l / CH][l % CH] = g_comb[bh * CH * CH + l];
    __syncthreads();

    float wr[CH];
    #pragma unroll
    for (int c = 0; c < CH; ++c) wr[c] = wproj[o * KDIM + hh * CH + c];

    __nv_bfloat16* eh = g_weh + ((size_t)b * DIM + o) * KDIM + hh * CH;
    __nv_bfloat16* el = g_wel + ((size_t)b * DIM + o) * KDIM + hh * CH;
    for (int d = 0; d < CH; ++d) {
        float s = 0.f;
        #pragma unroll
        for (int c = 0; c < CH; ++c) s = fmaf(wr[c], cs[c][d], s);
        const __nv_bfloat16 h = __float2bfloat16(s);
        eh[d] = h;
        el[d] = __float2bfloat16(s - __bfloat162float(h));
    }
}

// ---------------- launch ----------------------------------------------------
extern "C" void kernel_launch(void* const* d_in, const int* in_sizes, int n_in,
                              void* d_out, int out_size)
{
    const float* x           = (const float*)d_in[0];  // [4,192,128,128]
    const float* w_qkv       = (const float*)d_in[1];  // [576,192]
    const float* w_dw        = (const float*)d_in[2];  // [576,9]
    const float* w_proj      = (const float*)d_in[3];  // [192,192]
    const float* temperature = (const float*)d_in[4];  // [4]
    const float* attn_w      = (const float*)d_in[5];  // [4]
    float* out = (float*)d_out;

    float* qkv; cudaGetSymbolAddress((void**)&qkv, g_qkv);
    float* dw;  cudaGetSymbolAddress((void**)&dw,  g_dw);
    __nv_bfloat16* wqh; cudaGetSymbolAddress((void**)&wqh, g_wqh);
    __nv_bfloat16* wql; cudaGetSymbolAddress((void**)&wql, g_wql);
    __nv_bfloat16* weh; cudaGetSymbolAddress((void**)&weh, g_weh);
    __nv_bfloat16* wel; cudaGetSymbolAddress((void**)&wel, g_wel);

    static bool attr_set = false;
    if (!attr_set) {
        cudaFuncSetAttribute(gemm_mma,
                             cudaFuncAttributeMaxDynamicSharedMemorySize,
                             G_SMEM_BYTES);
        attr_set = true;
    }

    // 0. split qkv weights into bf16 hi/lo + zero accumulators
    w_split<<<(MQKV * KDIM + 255) / 256, 256>>>(w_qkv);

    // 1. qkv = w_qkv @ x  (tensor cores, shared weights across batch)
    gemm_mma<<<dim3(HW / 128, (MQKV + 127) / 128, BATCH), 256, G_SMEM_BYTES>>>(
        wqh, wql, x, qkv, MQKV, 0, (long)KDIM * HW, (long)MQKV * HW);

    // 2. depthwise 3x3 (smem-tiled)
    dwconv3x3_t<<<dim3(HH / DW_TH, BATCH * MQKV), 256>>>(qkv, w_dw, dw);

    // 3. attn partials (S, norms)
    attn_partial<<<dim3(BHN, 64), 256>>>();

    // 4. combined attention weights (topk + softmax + weighted sum)
    finalize_comb<<<BHN, 64>>>(temperature, attn_w);

    // 5. W_eff[b] = W_proj . blockdiag(comb_b)  (fuses attn_apply into proj)
    weff_compute<<<BHN, 192>>>(w_proj);

    // 6. out = W_eff[b] @ v  (tensor cores, per-batch weights, v from g_dw)
    gemm_mma<<<dim3(HW / 128, (DIM + 127) / 128, BATCH), 256, G_SMEM_BYTES>>>(
        weh, wel, dw + (size_t)2 * DIM * HW, out, DIM,
        (long)DIM * KDIM, (long)MQKV * HW, (long)DIM * HW);
}